// round 5
// baseline (speedup 1.0000x reference)
#include <cuda_runtime.h>
#include <cuda_bf16.h>
#include <cstdint>

#define C_CH   128
#define HW     16384
#define BATCH  8
#define QKV_CH 384
#define NHEAD  8
#define DH     16
#define NCHUNK 16

// ===================== scratch ==============================================
__device__ float g_qkv  [(long)BATCH * QKV_CH * HW];
__device__ float g_qkv2 [(long)BATCH * QKV_CH * HW];
__device__ float g_part [64 * NCHUNK * 288];
__device__ float g_attn [64 * 256];
__device__ __align__(16) __nv_bfloat16 g_xhi [(long)BATCH * C_CH * HW];
__device__ __align__(16) __nv_bfloat16 g_xlo [(long)BATCH * C_CH * HW];
__device__ __align__(16) __nv_bfloat16 g_chi [(long)BATCH * C_CH * HW];
__device__ __align__(16) __nv_bfloat16 g_clo [(long)BATCH * C_CH * HW];
__device__ __align__(16) __nv_bfloat16 g_whi [QKV_CH * C_CH + C_CH * C_CH];
__device__ __align__(16) __nv_bfloat16 g_wlo [QKV_CH * C_CH + C_CH * C_CH];

// ===================== PTX helpers ==========================================
__device__ __forceinline__ uint32_t smem_u32(const void* p) {
    uint32_t a;
    asm("{ .reg .u64 t; cvta.to.shared.u64 t, %1; cvt.u32.u64 %0, t; }" : "=r"(a) : "l"(p));
    return a;
}
__device__ __forceinline__ void ldsm_x4(uint32_t* r, uint32_t addr) {
    asm volatile("ldmatrix.sync.aligned.m8n8.x4.shared.b16 {%0,%1,%2,%3}, [%4];"
                 : "=r"(r[0]), "=r"(r[1]), "=r"(r[2]), "=r"(r[3]) : "r"(addr));
}
__device__ __forceinline__ void ldsm_x4_t(uint32_t* r, uint32_t addr) {
    asm volatile("ldmatrix.sync.aligned.m8n8.x4.trans.shared.b16 {%0,%1,%2,%3}, [%4];"
                 : "=r"(r[0]), "=r"(r[1]), "=r"(r[2]), "=r"(r[3]) : "r"(addr));
}
__device__ __forceinline__ void mma_bf16(float* d, const uint32_t* a, const uint32_t* b) {
    asm volatile(
        "mma.sync.aligned.m16n8k16.row.col.f32.bf16.bf16.f32 "
        "{%0,%1,%2,%3}, {%4,%5,%6,%7}, {%8,%9}, {%0,%1,%2,%3};"
        : "+f"(d[0]), "+f"(d[1]), "+f"(d[2]), "+f"(d[3])
        : "r"(a[0]), "r"(a[1]), "r"(a[2]), "r"(a[3]), "r"(b[0]), "r"(b[1]));
}
__device__ __forceinline__ void cp_async16(uint32_t dst, const void* src) {
    asm volatile("cp.async.ca.shared.global [%0], [%1], 16;" :: "r"(dst), "l"(src));
}
#define CP_COMMIT() asm volatile("cp.async.commit_group;" ::: "memory")
#define CP_WAIT(n)  asm volatile("cp.async.wait_group %0;" :: "n"(n) : "memory")

// ===================== split kernel: f32 -> bf16 hi + lo ====================
// n must be a multiple of 1024 (processes 4 f32 per thread).
__global__ void __launch_bounds__(256) cvt_split(
    const float* __restrict__ in,
    __nv_bfloat16* __restrict__ hi, __nv_bfloat16* __restrict__ lo)
{
    const long i4 = (long)blockIdx.x * 256 + threadIdx.x;
    const float4 v = ((const float4*)in)[i4];
    __nv_bfloat16 h0 = __float2bfloat16(v.x), h1 = __float2bfloat16(v.y);
    __nv_bfloat16 h2 = __float2bfloat16(v.z), h3 = __float2bfloat16(v.w);
    __nv_bfloat16 l0 = __float2bfloat16(v.x - __bfloat162float(h0));
    __nv_bfloat16 l1 = __float2bfloat16(v.y - __bfloat162float(h1));
    __nv_bfloat16 l2 = __float2bfloat16(v.z - __bfloat162float(h2));
    __nv_bfloat16 l3 = __float2bfloat16(v.w - __bfloat162float(h3));
    __nv_bfloat162 hp0; hp0.x = h0; hp0.y = h1;
    __nv_bfloat162 hp1; hp1.x = h2; hp1.y = h3;
    __nv_bfloat162 lp0; lp0.x = l0; lp0.y = l1;
    __nv_bfloat162 lp1; lp1.x = l2; lp1.y = l3;
    ((uint2*)hi)[i4] = make_uint2(*(uint32_t*)&hp0, *(uint32_t*)&hp1);
    ((uint2*)lo)[i4] = make_uint2(*(uint32_t*)&lp0, *(uint32_t*)&lp1);
}

// ===================== tensor-core GEMM (pre-split bf16, cp.async pipe) ======
// C[z][o][n] = sum_c W[o][c] * X[z][c][n]; block tile 128(o) x 128(n).
// K = 128 in 4 chunks of 32, 2-stage cp.async double buffer.
// 8 warps (2m x 4n), warp tile 64x32; passes hh + hl + lh, fp32 acc.
#define KCH      32
#define W_STRIDE 40     // bf16 elems; 80B rows (odd x16B) conflict-free
#define X_STRIDE 136    // 272B rows conflict-free
#define ST_WHI   0
#define ST_WLO   10240  // 128*40*2
#define ST_XHI   20480
#define ST_XLO   29184  // +32*136*2
#define ST_SIZE  37888
#define SM_GEMM  (2 * ST_SIZE)   // 75776 B -> 2 CTAs/SM

__global__ void __launch_bounds__(256, 2) gemm_bf3(
    const __nv_bfloat16* __restrict__ Whi, const __nv_bfloat16* __restrict__ Wlo,
    const __nv_bfloat16* __restrict__ Xhi_g, const __nv_bfloat16* __restrict__ Xlo_g,
    float* __restrict__ Cg, int Mw)
{
    extern __shared__ char sm[];
    const uint32_t smb = smem_u32(sm);

    const int tid  = threadIdx.x;
    const int lane = tid & 31;
    const int wid  = tid >> 5;
    const int wm   = wid >> 2;
    const int wn   = wid & 3;

    const int n0 = blockIdx.x * 128;
    const int m0 = blockIdx.y * 128;
    const __nv_bfloat16* Xhi = Xhi_g + (long)blockIdx.z * C_CH * HW;
    const __nv_bfloat16* Xlo = Xlo_g + (long)blockIdx.z * C_CH * HW;
    float* C = Cg + (long)blockIdx.z * (long)Mw * HW;

    float acc[4][4][4];
    #pragma unroll
    for (int i = 0; i < 4; i++)
        #pragma unroll
        for (int j = 0; j < 4; j++)
            #pragma unroll
            for (int r = 0; r < 4; r++) acc[i][j][r] = 0.f;

    const int a_row = (lane & 7) + ((lane >> 3) & 1) * 8;
    const int a_col = (lane >> 4) * 8;
    const int b_row = (lane & 7) + ((lane >> 3) & 1) * 8;
    const int b_col = (lane >> 4) * 8;

    // ---- async chunk loader: 8 x 16B cp.async per thread ----
    auto load_chunk = [&](int kc, uint32_t stg) {
        const int k0 = kc * KCH;
        // W: 128 rows x 4 segs x 2 splits = 1024 copies
        #pragma unroll
        for (int t = 0; t < 4; t++) {
            const int lin  = t * 256 + tid;
            const int row  = lin >> 3;
            const int spl  = (lin >> 2) & 1;
            const int seg  = lin & 3;
            const __nv_bfloat16* src =
                (spl ? Wlo : Whi) + (long)(m0 + row) * 128 + k0 + seg * 8;
            const uint32_t dst = smb + stg + (spl ? ST_WLO : ST_WHI)
                               + (row * W_STRIDE + seg * 8) * 2;
            cp_async16(dst, src);
        }
        // X: 32 rows x 16 segs x 2 splits = 1024 copies
        #pragma unroll
        for (int t = 0; t < 4; t++) {
            const int lin  = t * 256 + tid;
            const int row  = lin >> 5;
            const int spl  = (lin >> 4) & 1;
            const int seg  = lin & 15;
            const __nv_bfloat16* src =
                (spl ? Xlo : Xhi) + (long)(k0 + row) * HW + n0 + seg * 8;
            const uint32_t dst = smb + stg + (spl ? ST_XLO : ST_XHI)
                               + (row * X_STRIDE + seg * 8) * 2;
            cp_async16(dst, src);
        }
    };

    load_chunk(0, 0);
    CP_COMMIT();

    #pragma unroll
    for (int kc = 0; kc < 4; kc++) {
        const uint32_t cur = (uint32_t)(kc & 1) * ST_SIZE;
        if (kc < 3) {
            load_chunk(kc + 1, (uint32_t)((kc + 1) & 1) * ST_SIZE);
            CP_COMMIT();
            CP_WAIT(1);
        } else {
            CP_WAIT(0);
        }
        __syncthreads();

        #pragma unroll
        for (int ks = 0; ks < 2; ks++) {
            const int kk = ks * 16;
            uint32_t a[4][4], bh[2][4], bl[2][4];

            #pragma unroll
            for (int u = 0; u < 2; u++) {
                const int r = kk + b_row;
                const int c = wn * 32 + u * 16 + b_col;
                ldsm_x4_t(bh[u], smb + cur + ST_XHI + (r * X_STRIDE + c) * 2);
                ldsm_x4_t(bl[u], smb + cur + ST_XLO + (r * X_STRIDE + c) * 2);
            }
            #pragma unroll
            for (int i = 0; i < 4; i++) {
                const int r = wm * 64 + i * 16 + a_row;
                ldsm_x4(a[i], smb + cur + ST_WHI + (r * W_STRIDE + kk + a_col) * 2);
            }
            #pragma unroll
            for (int i = 0; i < 4; i++)
                #pragma unroll
                for (int j = 0; j < 4; j++) {
                    mma_bf16(acc[i][j], a[i], &bh[j >> 1][(j & 1) * 2]);
                    mma_bf16(acc[i][j], a[i], &bl[j >> 1][(j & 1) * 2]);
                }
            #pragma unroll
            for (int i = 0; i < 4; i++) {
                const int r = wm * 64 + i * 16 + a_row;
                ldsm_x4(a[i], smb + cur + ST_WLO + (r * W_STRIDE + kk + a_col) * 2);
            }
            #pragma unroll
            for (int i = 0; i < 4; i++)
                #pragma unroll
                for (int j = 0; j < 4; j++)
                    mma_bf16(acc[i][j], a[i], &bh[j >> 1][(j & 1) * 2]);
        }
        __syncthreads();
    }

    // ---- epilogue ----
    const int mw = m0 + wm * 64;
    const int nw = n0 + wn * 32;
    #pragma unroll
    for (int i = 0; i < 4; i++) {
        #pragma unroll
        for (int j = 0; j < 4; j++) {
            const int row0 = mw + i * 16 + (lane >> 2);
            const int col  = nw + j * 8 + (lane & 3) * 2;
            *(float2*)&C[(long)row0 * HW + col]       = make_float2(acc[i][j][0], acc[i][j][1]);
            *(float2*)&C[(long)(row0 + 8) * HW + col] = make_float2(acc[i][j][2], acc[i][j][3]);
        }
    }
}

// ===================== depthwise 3x3 ========================================
__global__ void __launch_bounds__(256) dwconv3x3(
    const float* __restrict__ in, const float* __restrict__ w, float* __restrict__ out)
{
    const int n  = blockIdx.x * 256 + threadIdx.x;
    const int bc = blockIdx.y;
    const int ch = bc % QKV_CH;
    const int y  = n >> 7;
    const int x  = n & 127;
    const float* ip = in + (long)bc * HW;
    const float* wp = w + ch * 9;
    float s = 0.f;
    #pragma unroll
    for (int dy = -1; dy <= 1; dy++) {
        const int yy = y + dy;
        if (yy < 0 || yy > 127) continue;
        #pragma unroll
        for (int dx = -1; dx <= 1; dx++) {
            const int xx = x + dx;
            if (xx < 0 || xx > 127) continue;
            s += ip[yy * 128 + xx] * wp[(dy + 1) * 3 + (dx + 1)];
        }
    }
    out[(long)bc * HW + n] = s;
}

// ===================== gram partials ========================================
__global__ void __launch_bounds__(256) gram16(
    const float* __restrict__ qkv2, float* __restrict__ partials)
{
    const int bh = blockIdx.y;
    const int b  = bh >> 3, hd = bh & 7;
    const int n0 = blockIdx.x * 1024;
    const float* qg = qkv2 + (long)b * QKV_CH * HW + (long)hd * DH * HW + n0;
    const float* kg = qg + (long)C_CH * HW;

    __shared__ float qs[16 * 129];
    __shared__ float ks[16 * 129];
    const int tid = threadIdx.x;
    const int i = tid >> 4, j = tid & 15;
    float acc = 0.f, nacc = 0.f;

    for (int t0 = 0; t0 < 1024; t0 += 128) {
        #pragma unroll
        for (int idx = tid; idx < 2048; idx += 256) {
            const int r = idx >> 7, c = idx & 127;
            qs[r * 129 + c] = qg[(long)r * HW + t0 + c];
            ks[r * 129 + c] = kg[(long)r * HW + t0 + c];
        }
        __syncthreads();
        #pragma unroll 8
        for (int t = 0; t < 128; t++)
            acc += qs[i * 129 + t] * ks[j * 129 + t];
        if (tid < 16) {
            #pragma unroll 8
            for (int t = 0; t < 128; t++) { float v = qs[tid * 129 + t]; nacc += v * v; }
        } else if (tid < 32) {
            #pragma unroll 8
            for (int t = 0; t < 128; t++) { float v = ks[(tid - 16) * 129 + t]; nacc += v * v; }
        }
        __syncthreads();
    }
    float* p = partials + ((long)bh * NCHUNK + blockIdx.x) * 288;
    p[tid] = acc;
    if (tid < 32) p[256 + tid] = nacc;
}

// ===================== softmax ==============================================
__global__ void __launch_bounds__(256) attn_softmax(
    const float* __restrict__ partials, const float* __restrict__ temperature,
    float* __restrict__ attn)
{
    const int bh = blockIdx.x;
    const int hd = bh & 7;
    __shared__ float S[256];
    __shared__ float qn[16], kn[16];
    const int tid = threadIdx.x;
    float s = 0.f;
    #pragma unroll
    for (int c = 0; c < NCHUNK; c++)
        s += partials[((long)bh * NCHUNK + c) * 288 + tid];
    S[tid] = s;
    if (tid < 32) {
        float ns = 0.f;
        #pragma unroll
        for (int c = 0; c < NCHUNK; c++)
            ns += partials[((long)bh * NCHUNK + c) * 288 + 256 + tid];
        const float nv = fmaxf(sqrtf(ns), 1e-12f);
        if (tid < 16) qn[tid] = nv; else kn[tid - 16] = nv;
    }
    __syncthreads();
    if (tid < 16) {
        const int   i  = tid;
        const float tp = temperature[hd];
        float lg[16];
        float mx = -1e30f;
        #pragma unroll
        for (int j = 0; j < 16; j++) {
            lg[j] = S[i * 16 + j] / (qn[i] * kn[j]) * tp;
            mx = fmaxf(mx, lg[j]);
        }
        float sum = 0.f;
        #pragma unroll
        for (int j = 0; j < 16; j++) { lg[j] = expf(lg[j] - mx); sum += lg[j]; }
        const float inv = 1.f / sum;
        #pragma unroll
        for (int j = 0; j < 16; j++)
            attn[(long)bh * 256 + i * 16 + j] = lg[j] * inv;
    }
}

// ===================== attn apply (writes bf16 hi/lo ctx) ====================
__global__ void __launch_bounds__(256) attn_apply_split(
    const float* __restrict__ qkv2, const float* __restrict__ illu,
    const float* __restrict__ attn,
    __nv_bfloat16* __restrict__ chi, __nv_bfloat16* __restrict__ clo)
{
    const int bh = blockIdx.y;
    const int b  = bh >> 3, hd = bh & 7;
    __shared__ float a[256];
    a[threadIdx.x] = attn[(long)bh * 256 + threadIdx.x];
    __syncthreads();
    const int n = blockIdx.x * 256 + threadIdx.x;
    const float* v  = qkv2 + (long)b * QKV_CH * HW + (long)(2 * C_CH + hd * DH) * HW + n;
    const float* il = illu + (long)b * C_CH   * HW + (long)(hd * DH) * HW + n;
    float vv[16];
    #pragma unroll
    for (int j = 0; j < 16; j++)
        vv[j] = v[(long)j * HW] * il[(long)j * HW];
    const long obase = (long)b * C_CH * HW + (long)(hd * DH) * HW + n;
    #pragma unroll
    for (int i = 0; i < 16; i++) {
        float s = 0.f;
        #pragma unroll
        for (int j = 0; j < 16; j++)
            s += a[i * 16 + j] * vv[j];
        const __nv_bfloat16 h = __float2bfloat16(s);
        const __nv_bfloat16 l = __float2bfloat16(s - __bfloat162float(h));
        chi[obase + (long)i * HW] = h;
        clo[obase + (long)i * HW] = l;
    }
}

// ===================== launch ===============================================
extern "C" void kernel_launch(void* const* d_in, const int* in_sizes, int n_in,
                              void* d_out, int out_size)
{
    const float* x_in   = (const float*)d_in[0];
    const float* illu   = (const float*)d_in[1];
    const float* w_qkv  = (const float*)d_in[2];
    const float* w_dw   = (const float*)d_in[3];
    const float* w_proj = (const float*)d_in[4];
    const float* temp   = (const float*)d_in[5];
    float* out = (float*)d_out;

    float *qkv, *qkv2, *part, *attn;
    __nv_bfloat16 *xhi, *xlo, *chi, *clo, *whi, *wlo;
    cudaGetSymbolAddress((void**)&qkv,  g_qkv);
    cudaGetSymbolAddress((void**)&qkv2, g_qkv2);
    cudaGetSymbolAddress((void**)&part, g_part);
    cudaGetSymbolAddress((void**)&attn, g_attn);
    cudaGetSymbolAddress((void**)&xhi,  g_xhi);
    cudaGetSymbolAddress((void**)&xlo,  g_xlo);
    cudaGetSymbolAddress((void**)&chi,  g_chi);
    cudaGetSymbolAddress((void**)&clo,  g_clo);
    cudaGetSymbolAddress((void**)&whi,  g_whi);
    cudaGetSymbolAddress((void**)&wlo,  g_wlo);

    cudaFuncSetAttribute(gemm_bf3, cudaFuncAttributeMaxDynamicSharedMemorySize, SM_GEMM);

    // 0) pre-split weights + input to bf16 hi/lo
    cvt_split<<<QKV_CH * C_CH / 1024, 256>>>(w_qkv, whi, wlo);
    cvt_split<<<C_CH * C_CH / 1024, 256>>>(w_proj, whi + QKV_CH * C_CH, wlo + QKV_CH * C_CH);
    cvt_split<<<BATCH * C_CH * HW / 1024, 256>>>(x_in, xhi, xlo);
    // 1) qkv = w_qkv @ x   (per batch: Mw=384, K=128, N=16384)
    gemm_bf3<<<dim3(HW / 128, QKV_CH / 128, BATCH), 256, SM_GEMM>>>(whi, wlo, xhi, xlo, qkv, QKV_CH);
    // 2) depthwise 3x3 SAME
    dwconv3x3<<<dim3(HW / 256, BATCH * QKV_CH), 256>>>(qkv, w_dw, qkv2);
    // 3) gram partials + norms
    gram16<<<dim3(NCHUNK, 64), 256>>>(qkv2, part);
    // 4) softmax(16x16) with l2-normalization and temperature
    attn_softmax<<<64, 256>>>(part, temp, attn);
    // 5) ctx = attn @ (v * illu), written as bf16 hi/lo
    attn_apply_split<<<dim3(HW / 256, 64), 256>>>(qkv2, illu, attn, chi, clo);
    // 6) out = w_proj @ ctx (per batch: Mw=128)
    gemm_bf3<<<dim3(HW / 128, C_CH / 128, BATCH), 256, SM_GEMM>>>(
        whi + QKV_CH * C_CH, wlo + QKV_CH * C_CH, chi, clo, out, C_CH);
}

// round 6
// speedup vs baseline: 1.3111x; 1.3111x over previous
#include <cuda_runtime.h>
#include <cuda_bf16.h>
#include <cstdint>

#define C_CH   128
#define HW     16384
#define BATCH  8
#define QKV_CH 384
#define NHEAD  8
#define DH     16
#define NCHUNK 16

// ===================== scratch ==============================================
__device__ float g_qkv  [(long)BATCH * QKV_CH * HW];
__device__ float g_qkv2 [(long)BATCH * QKV_CH * HW];
__device__ float g_part [64 * NCHUNK * 288];
__device__ float g_attn [64 * 256];
__device__ __align__(16) __nv_bfloat16 g_xhi [(long)BATCH * C_CH * HW];
__device__ __align__(16) __nv_bfloat16 g_xlo [(long)BATCH * C_CH * HW];
__device__ __align__(16) __nv_bfloat16 g_chi [(long)BATCH * C_CH * HW];
__device__ __align__(16) __nv_bfloat16 g_clo [(long)BATCH * C_CH * HW];
__device__ __align__(16) __nv_bfloat16 g_whi [QKV_CH * C_CH + C_CH * C_CH];
__device__ __align__(16) __nv_bfloat16 g_wlo [QKV_CH * C_CH + C_CH * C_CH];

// ===================== PTX helpers ==========================================
__device__ __forceinline__ uint32_t smem_u32(const void* p) {
    uint32_t a;
    asm("{ .reg .u64 t; cvta.to.shared.u64 t, %1; cvt.u32.u64 %0, t; }" : "=r"(a) : "l"(p));
    return a;
}
__device__ __forceinline__ void ldsm_x4(uint32_t* r, uint32_t addr) {
    asm volatile("ldmatrix.sync.aligned.m8n8.x4.shared.b16 {%0,%1,%2,%3}, [%4];"
                 : "=r"(r[0]), "=r"(r[1]), "=r"(r[2]), "=r"(r[3]) : "r"(addr));
}
__device__ __forceinline__ void ldsm_x4_t(uint32_t* r, uint32_t addr) {
    asm volatile("ldmatrix.sync.aligned.m8n8.x4.trans.shared.b16 {%0,%1,%2,%3}, [%4];"
                 : "=r"(r[0]), "=r"(r[1]), "=r"(r[2]), "=r"(r[3]) : "r"(addr));
}
__device__ __forceinline__ void mma_bf16(float* d, const uint32_t* a, const uint32_t* b) {
    asm volatile(
        "mma.sync.aligned.m16n8k16.row.col.f32.bf16.bf16.f32 "
        "{%0,%1,%2,%3}, {%4,%5,%6,%7}, {%8,%9}, {%0,%1,%2,%3};"
        : "+f"(d[0]), "+f"(d[1]), "+f"(d[2]), "+f"(d[3])
        : "r"(a[0]), "r"(a[1]), "r"(a[2]), "r"(a[3]), "r"(b[0]), "r"(b[1]));
}
__device__ __forceinline__ void cp_async16(uint32_t dst, const void* src) {
    asm volatile("cp.async.ca.shared.global [%0], [%1], 16;" :: "r"(dst), "l"(src));
}
#define CP_COMMIT() asm volatile("cp.async.commit_group;" ::: "memory")
#define CP_WAIT(n)  asm volatile("cp.async.wait_group %0;" :: "n"(n) : "memory")

// ===================== split kernel: f32 -> bf16 hi + lo ====================
__global__ void __launch_bounds__(256) cvt_split(
    const float* __restrict__ in,
    __nv_bfloat16* __restrict__ hi, __nv_bfloat16* __restrict__ lo)
{
    const long i4 = (long)blockIdx.x * 256 + threadIdx.x;
    const float4 v = ((const float4*)in)[i4];
    __nv_bfloat16 h0 = __float2bfloat16(v.x), h1 = __float2bfloat16(v.y);
    __nv_bfloat16 h2 = __float2bfloat16(v.z), h3 = __float2bfloat16(v.w);
    __nv_bfloat16 l0 = __float2bfloat16(v.x - __bfloat162float(h0));
    __nv_bfloat16 l1 = __float2bfloat16(v.y - __bfloat162float(h1));
    __nv_bfloat16 l2 = __float2bfloat16(v.z - __bfloat162float(h2));
    __nv_bfloat16 l3 = __float2bfloat16(v.w - __bfloat162float(h3));
    __nv_bfloat162 hp0; hp0.x = h0; hp0.y = h1;
    __nv_bfloat162 hp1; hp1.x = h2; hp1.y = h3;
    __nv_bfloat162 lp0; lp0.x = l0; lp0.y = l1;
    __nv_bfloat162 lp1; lp1.x = l2; lp1.y = l3;
    ((uint2*)hi)[i4] = make_uint2(*(uint32_t*)&hp0, *(uint32_t*)&hp1);
    ((uint2*)lo)[i4] = make_uint2(*(uint32_t*)&lp0, *(uint32_t*)&lp1);
}

// ===================== tensor-core GEMM (pre-split bf16, cp.async pipe) ======
#define KCH      32
#define W_STRIDE 40
#define X_STRIDE 136
#define ST_WHI   0
#define ST_WLO   10240
#define ST_XHI   20480
#define ST_XLO   29184
#define ST_SIZE  37888
#define SM_GEMM  (2 * ST_SIZE)

__global__ void __launch_bounds__(256, 2) gemm_bf3(
    const __nv_bfloat16* __restrict__ Whi, const __nv_bfloat16* __restrict__ Wlo,
    const __nv_bfloat16* __restrict__ Xhi_g, const __nv_bfloat16* __restrict__ Xlo_g,
    float* __restrict__ Cg, int Mw)
{
    extern __shared__ char sm[];
    const uint32_t smb = smem_u32(sm);

    const int tid  = threadIdx.x;
    const int lane = tid & 31;
    const int wid  = tid >> 5;
    const int wm   = wid >> 2;
    const int wn   = wid & 3;

    const int n0 = blockIdx.x * 128;
    const int m0 = blockIdx.y * 128;
    const __nv_bfloat16* Xhi = Xhi_g + (long)blockIdx.z * C_CH * HW;
    const __nv_bfloat16* Xlo = Xlo_g + (long)blockIdx.z * C_CH * HW;
    float* C = Cg + (long)blockIdx.z * (long)Mw * HW;

    float acc[4][4][4];
    #pragma unroll
    for (int i = 0; i < 4; i++)
        #pragma unroll
        for (int j = 0; j < 4; j++)
            #pragma unroll
            for (int r = 0; r < 4; r++) acc[i][j][r] = 0.f;

    const int a_row = (lane & 7) + ((lane >> 3) & 1) * 8;
    const int a_col = (lane >> 4) * 8;
    const int b_row = (lane & 7) + ((lane >> 3) & 1) * 8;
    const int b_col = (lane >> 4) * 8;

    auto load_chunk = [&](int kc, uint32_t stg) {
        const int k0 = kc * KCH;
        #pragma unroll
        for (int t = 0; t < 4; t++) {
            const int lin  = t * 256 + tid;
            const int row  = lin >> 3;
            const int spl  = (lin >> 2) & 1;
            const int seg  = lin & 3;
            const __nv_bfloat16* src =
                (spl ? Wlo : Whi) + (long)(m0 + row) * 128 + k0 + seg * 8;
            const uint32_t dst = smb + stg + (spl ? ST_WLO : ST_WHI)
                               + (row * W_STRIDE + seg * 8) * 2;
            cp_async16(dst, src);
        }
        #pragma unroll
        for (int t = 0; t < 4; t++) {
            const int lin  = t * 256 + tid;
            const int row  = lin >> 5;
            const int spl  = (lin >> 4) & 1;
            const int seg  = lin & 15;
            const __nv_bfloat16* src =
                (spl ? Xlo : Xhi) + (long)(k0 + row) * HW + n0 + seg * 8;
            const uint32_t dst = smb + stg + (spl ? ST_XLO : ST_XHI)
                               + (row * X_STRIDE + seg * 8) * 2;
            cp_async16(dst, src);
        }
    };

    load_chunk(0, 0);
    CP_COMMIT();

    #pragma unroll
    for (int kc = 0; kc < 4; kc++) {
        const uint32_t cur = (uint32_t)(kc & 1) * ST_SIZE;
        if (kc < 3) {
            load_chunk(kc + 1, (uint32_t)((kc + 1) & 1) * ST_SIZE);
            CP_COMMIT();
            CP_WAIT(1);
        } else {
            CP_WAIT(0);
        }
        __syncthreads();

        #pragma unroll
        for (int ks = 0; ks < 2; ks++) {
            const int kk = ks * 16;
            uint32_t a[4][4], bh[2][4], bl[2][4];

            #pragma unroll
            for (int u = 0; u < 2; u++) {
                const int r = kk + b_row;
                const int c = wn * 32 + u * 16 + b_col;
                ldsm_x4_t(bh[u], smb + cur + ST_XHI + (r * X_STRIDE + c) * 2);
                ldsm_x4_t(bl[u], smb + cur + ST_XLO + (r * X_STRIDE + c) * 2);
            }
            #pragma unroll
            for (int i = 0; i < 4; i++) {
                const int r = wm * 64 + i * 16 + a_row;
                ldsm_x4(a[i], smb + cur + ST_WHI + (r * W_STRIDE + kk + a_col) * 2);
            }
            #pragma unroll
            for (int i = 0; i < 4; i++)
                #pragma unroll
                for (int j = 0; j < 4; j++) {
                    mma_bf16(acc[i][j], a[i], &bh[j >> 1][(j & 1) * 2]);
                    mma_bf16(acc[i][j], a[i], &bl[j >> 1][(j & 1) * 2]);
                }
            #pragma unroll
            for (int i = 0; i < 4; i++) {
                const int r = wm * 64 + i * 16 + a_row;
                ldsm_x4(a[i], smb + cur + ST_WLO + (r * W_STRIDE + kk + a_col) * 2);
            }
            #pragma unroll
            for (int i = 0; i < 4; i++)
                #pragma unroll
                for (int j = 0; j < 4; j++)
                    mma_bf16(acc[i][j], a[i], &bh[j >> 1][(j & 1) * 2]);
        }
        __syncthreads();
    }

    const int mw = m0 + wm * 64;
    const int nw = n0 + wn * 32;
    #pragma unroll
    for (int i = 0; i < 4; i++) {
        #pragma unroll
        for (int j = 0; j < 4; j++) {
            const int row0 = mw + i * 16 + (lane >> 2);
            const int col  = nw + j * 8 + (lane & 3) * 2;
            *(float2*)&C[(long)row0 * HW + col]       = make_float2(acc[i][j][0], acc[i][j][1]);
            *(float2*)&C[(long)(row0 + 8) * HW + col] = make_float2(acc[i][j][2], acc[i][j][3]);
        }
    }
}

// ===================== depthwise 3x3 (SMEM-tiled, vectorized) ================
// block = one (batch*channel) x 8 output rows; 256 threads, 4 outputs each.
// 10 input rows staged in SMEM via float4; ~2 float4 LDG per thread total.
__global__ void __launch_bounds__(256) dwconv3x3(
    const float* __restrict__ in,   // [B*384][128][128]
    const float* __restrict__ w,    // [384][1][3][3]
    float* __restrict__ out)
{
    __shared__ float s[10][128];

    const int bc = blockIdx.y;
    const int y0 = blockIdx.x * 8;
    const int ch = bc % QKV_CH;
    const int tid = threadIdx.x;

    const float* ip = in + (long)bc * HW;

    // stage rows y0-1 .. y0+8 (zeros outside image)
    #pragma unroll
    for (int t = tid; t < 320; t += 256) {
        const int r  = t >> 5;          // 0..9
        const int c4 = (t & 31) * 4;    // 0..124
        const int gy = y0 - 1 + r;
        float4 v = make_float4(0.f, 0.f, 0.f, 0.f);
        if (gy >= 0 && gy < 128) v = *(const float4*)&ip[gy * 128 + c4];
        *(float4*)&s[r][c4] = v;
    }

    // weights (broadcast, L1-hot)
    const float* wp = w + ch * 9;
    const float w00 = wp[0], w01 = wp[1], w02 = wp[2];
    const float w10 = wp[3], w11 = wp[4], w12 = wp[5];
    const float w20 = wp[6], w21 = wp[7], w22 = wp[8];
    __syncthreads();

    const int oy = tid >> 5;            // 0..7
    const int x  = (tid & 31) * 4;      // 0..124

    float o0 = 0.f, o1 = 0.f, o2 = 0.f, o3 = 0.f;
    #pragma unroll
    for (int dy = 0; dy < 3; dy++) {
        const float* row = s[oy + dy];
        const float4 v = *(const float4*)&row[x];
        const float vl = (x > 0)   ? row[x - 1] : 0.f;
        const float vr = (x < 124) ? row[x + 4] : 0.f;
        const float wa = (dy == 0) ? w00 : (dy == 1) ? w10 : w20;
        const float wb = (dy == 0) ? w01 : (dy == 1) ? w11 : w21;
        const float wc = (dy == 0) ? w02 : (dy == 1) ? w12 : w22;
        o0 += vl  * wa + v.x * wb + v.y * wc;
        o1 += v.x * wa + v.y * wb + v.z * wc;
        o2 += v.y * wa + v.z * wb + v.w * wc;
        o3 += v.z * wa + v.w * wb + vr  * wc;
    }
    *(float4*)&out[(long)bc * HW + (y0 + oy) * 128 + x] = make_float4(o0, o1, o2, o3);
}

// ===================== gram partials ========================================
__global__ void __launch_bounds__(256) gram16(
    const float* __restrict__ qkv2, float* __restrict__ partials)
{
    const int bh = blockIdx.y;
    const int b  = bh >> 3, hd = bh & 7;
    const int n0 = blockIdx.x * 1024;
    const float* qg = qkv2 + (long)b * QKV_CH * HW + (long)hd * DH * HW + n0;
    const float* kg = qg + (long)C_CH * HW;

    __shared__ float qs[16 * 129];
    __shared__ float ks[16 * 129];
    const int tid = threadIdx.x;
    const int i = tid >> 4, j = tid & 15;
    float acc = 0.f, nacc = 0.f;

    for (int t0 = 0; t0 < 1024; t0 += 128) {
        #pragma unroll
        for (int idx = tid; idx < 2048; idx += 256) {
            const int r = idx >> 7, c = idx & 127;
            qs[r * 129 + c] = qg[(long)r * HW + t0 + c];
            ks[r * 129 + c] = kg[(long)r * HW + t0 + c];
        }
        __syncthreads();
        #pragma unroll 8
        for (int t = 0; t < 128; t++)
            acc += qs[i * 129 + t] * ks[j * 129 + t];
        if (tid < 16) {
            #pragma unroll 8
            for (int t = 0; t < 128; t++) { float v = qs[tid * 129 + t]; nacc += v * v; }
        } else if (tid < 32) {
            #pragma unroll 8
            for (int t = 0; t < 128; t++) { float v = ks[(tid - 16) * 129 + t]; nacc += v * v; }
        }
        __syncthreads();
    }
    float* p = partials + ((long)bh * NCHUNK + blockIdx.x) * 288;
    p[tid] = acc;
    if (tid < 32) p[256 + tid] = nacc;
}

// ===================== softmax ==============================================
__global__ void __launch_bounds__(256) attn_softmax(
    const float* __restrict__ partials, const float* __restrict__ temperature,
    float* __restrict__ attn)
{
    const int bh = blockIdx.x;
    const int hd = bh & 7;
    __shared__ float S[256];
    __shared__ float qn[16], kn[16];
    const int tid = threadIdx.x;
    float s = 0.f;
    #pragma unroll
    for (int c = 0; c < NCHUNK; c++)
        s += partials[((long)bh * NCHUNK + c) * 288 + tid];
    S[tid] = s;
    if (tid < 32) {
        float ns = 0.f;
        #pragma unroll
        for (int c = 0; c < NCHUNK; c++)
            ns += partials[((long)bh * NCHUNK + c) * 288 + 256 + tid];
        const float nv = fmaxf(sqrtf(ns), 1e-12f);
        if (tid < 16) qn[tid] = nv; else kn[tid - 16] = nv;
    }
    __syncthreads();
    if (tid < 16) {
        const int   i  = tid;
        const float tp = temperature[hd];
        float lg[16];
        float mx = -1e30f;
        #pragma unroll
        for (int j = 0; j < 16; j++) {
            lg[j] = S[i * 16 + j] / (qn[i] * kn[j]) * tp;
            mx = fmaxf(mx, lg[j]);
        }
        float sum = 0.f;
        #pragma unroll
        for (int j = 0; j < 16; j++) { lg[j] = expf(lg[j] - mx); sum += lg[j]; }
        const float inv = 1.f / sum;
        #pragma unroll
        for (int j = 0; j < 16; j++)
            attn[(long)bh * 256 + i * 16 + j] = lg[j] * inv;
    }
}

// ===================== attn apply (writes bf16 hi/lo ctx) ====================
__global__ void __launch_bounds__(256) attn_apply_split(
    const float* __restrict__ qkv2, const float* __restrict__ illu,
    const float* __restrict__ attn,
    __nv_bfloat16* __restrict__ chi, __nv_bfloat16* __restrict__ clo)
{
    const int bh = blockIdx.y;
    const int b  = bh >> 3, hd = bh & 7;
    __shared__ float a[256];
    a[threadIdx.x] = attn[(long)bh * 256 + threadIdx.x];
    __syncthreads();
    const int n = blockIdx.x * 256 + threadIdx.x;
    const float* v  = qkv2 + (long)b * QKV_CH * HW + (long)(2 * C_CH + hd * DH) * HW + n;
    const float* il = illu + (long)b * C_CH   * HW + (long)(hd * DH) * HW + n;
    float vv[16];
    #pragma unroll
    for (int j = 0; j < 16; j++)
        vv[j] = v[(long)j * HW] * il[(long)j * HW];
    const long obase = (long)b * C_CH * HW + (long)(hd * DH) * HW + n;
    #pragma unroll
    for (int i = 0; i < 16; i++) {
        float s = 0.f;
        #pragma unroll
        for (int j = 0; j < 16; j++)
            s += a[i * 16 + j] * vv[j];
        const __nv_bfloat16 h = __float2bfloat16(s);
        const __nv_bfloat16 l = __float2bfloat16(s - __bfloat162float(h));
        chi[obase + (long)i * HW] = h;
        clo[obase + (long)i * HW] = l;
    }
}

// ===================== launch ===============================================
extern "C" void kernel_launch(void* const* d_in, const int* in_sizes, int n_in,
                              void* d_out, int out_size)
{
    const float* x_in   = (const float*)d_in[0];
    const float* illu   = (const float*)d_in[1];
    const float* w_qkv  = (const float*)d_in[2];
    const float* w_dw   = (const float*)d_in[3];
    const float* w_proj = (const float*)d_in[4];
    const float* temp   = (const float*)d_in[5];
    float* out = (float*)d_out;

    float *qkv, *qkv2, *part, *attn;
    __nv_bfloat16 *xhi, *xlo, *chi, *clo, *whi, *wlo;
    cudaGetSymbolAddress((void**)&qkv,  g_qkv);
    cudaGetSymbolAddress((void**)&qkv2, g_qkv2);
    cudaGetSymbolAddress((void**)&part, g_part);
    cudaGetSymbolAddress((void**)&attn, g_attn);
    cudaGetSymbolAddress((void**)&xhi,  g_xhi);
    cudaGetSymbolAddress((void**)&xlo,  g_xlo);
    cudaGetSymbolAddress((void**)&chi,  g_chi);
    cudaGetSymbolAddress((void**)&clo,  g_clo);
    cudaGetSymbolAddress((void**)&whi,  g_whi);
    cudaGetSymbolAddress((void**)&wlo,  g_wlo);

    cudaFuncSetAttribute(gemm_bf3, cudaFuncAttributeMaxDynamicSharedMemorySize, SM_GEMM);

    // 0) pre-split weights + input to bf16 hi/lo
    cvt_split<<<QKV_CH * C_CH / 1024, 256>>>(w_qkv, whi, wlo);
    cvt_split<<<C_CH * C_CH / 1024, 256>>>(w_proj, whi + QKV_CH * C_CH, wlo + QKV_CH * C_CH);
    cvt_split<<<BATCH * C_CH * HW / 1024, 256>>>(x_in, xhi, xlo);
    // 1) qkv = w_qkv @ x
    gemm_bf3<<<dim3(HW / 128, QKV_CH / 128, BATCH), 256, SM_GEMM>>>(whi, wlo, xhi, xlo, qkv, QKV_CH);
    // 2) depthwise 3x3 SAME (smem-tiled)
    dwconv3x3<<<dim3(16, BATCH * QKV_CH), 256>>>(qkv, w_dw, qkv2);
    // 3) gram partials + norms
    gram16<<<dim3(NCHUNK, 64), 256>>>(qkv2, part);
    // 4) softmax
    attn_softmax<<<64, 256>>>(part, temp, attn);
    // 5) ctx = attn @ (v * illu), written as bf16 hi/lo
    attn_apply_split<<<dim3(HW / 256, 64), 256>>>(qkv2, illu, attn, chi, clo);
    // 6) out = w_proj @ ctx
    gemm_bf3<<<dim3(HW / 128, C_CH / 128, BATCH), 256, SM_GEMM>>>(
        whi + QKV_CH * C_CH, wlo + QKV_CH * C_CH, chi, clo, out, C_CH);
}

// round 7
// speedup vs baseline: 1.5615x; 1.1910x over previous
#include <cuda_runtime.h>
#include <cuda_bf16.h>
#include <cstdint>

#define C_CH   128
#define HW     16384
#define BATCH  8
#define QKV_CH 384
#define NHEAD  8
#define DH     16
#define NCHUNK 16

// ===================== scratch ==============================================
__device__ float g_qkv  [(long)BATCH * QKV_CH * HW];
__device__ float g_qkv2 [(long)BATCH * QKV_CH * HW];
__device__ float g_part [64 * NCHUNK * 288];
__device__ float g_attn [64 * 256];
__device__ __align__(16) __nv_bfloat16 g_xhi [(long)BATCH * C_CH * HW];
__device__ __align__(16) __nv_bfloat16 g_xlo [(long)BATCH * C_CH * HW];
__device__ __align__(16) __nv_bfloat16 g_chi [(long)BATCH * C_CH * HW];
__device__ __align__(16) __nv_bfloat16 g_clo [(long)BATCH * C_CH * HW];
__device__ __align__(16) __nv_bfloat16 g_whi [QKV_CH * C_CH + C_CH * C_CH];
__device__ __align__(16) __nv_bfloat16 g_wlo [QKV_CH * C_CH + C_CH * C_CH];

// ===================== PTX helpers ==========================================
__device__ __forceinline__ uint32_t smem_u32(const void* p) {
    uint32_t a;
    asm("{ .reg .u64 t; cvta.to.shared.u64 t, %1; cvt.u32.u64 %0, t; }" : "=r"(a) : "l"(p));
    return a;
}
__device__ __forceinline__ void ldsm_x4(uint32_t* r, uint32_t addr) {
    asm volatile("ldmatrix.sync.aligned.m8n8.x4.shared.b16 {%0,%1,%2,%3}, [%4];"
                 : "=r"(r[0]), "=r"(r[1]), "=r"(r[2]), "=r"(r[3]) : "r"(addr));
}
__device__ __forceinline__ void ldsm_x4_t(uint32_t* r, uint32_t addr) {
    asm volatile("ldmatrix.sync.aligned.m8n8.x4.trans.shared.b16 {%0,%1,%2,%3}, [%4];"
                 : "=r"(r[0]), "=r"(r[1]), "=r"(r[2]), "=r"(r[3]) : "r"(addr));
}
__device__ __forceinline__ void mma_bf16(float* d, const uint32_t* a, const uint32_t* b) {
    asm volatile(
        "mma.sync.aligned.m16n8k16.row.col.f32.bf16.bf16.f32 "
        "{%0,%1,%2,%3}, {%4,%5,%6,%7}, {%8,%9}, {%0,%1,%2,%3};"
        : "+f"(d[0]), "+f"(d[1]), "+f"(d[2]), "+f"(d[3])
        : "r"(a[0]), "r"(a[1]), "r"(a[2]), "r"(a[3]), "r"(b[0]), "r"(b[1]));
}
__device__ __forceinline__ void cp_async16(uint32_t dst, const void* src) {
    asm volatile("cp.async.ca.shared.global [%0], [%1], 16;" :: "r"(dst), "l"(src));
}
#define CP_COMMIT() asm volatile("cp.async.commit_group;" ::: "memory")
#define CP_WAIT(n)  asm volatile("cp.async.wait_group %0;" :: "n"(n) : "memory")

// ===================== split kernel: f32 -> bf16 hi + lo ====================
__global__ void __launch_bounds__(256) cvt_split(
    const float* __restrict__ in,
    __nv_bfloat16* __restrict__ hi, __nv_bfloat16* __restrict__ lo)
{
    const long i4 = (long)blockIdx.x * 256 + threadIdx.x;
    const float4 v = ((const float4*)in)[i4];
    __nv_bfloat16 h0 = __float2bfloat16(v.x), h1 = __float2bfloat16(v.y);
    __nv_bfloat16 h2 = __float2bfloat16(v.z), h3 = __float2bfloat16(v.w);
    __nv_bfloat16 l0 = __float2bfloat16(v.x - __bfloat162float(h0));
    __nv_bfloat16 l1 = __float2bfloat16(v.y - __bfloat162float(h1));
    __nv_bfloat16 l2 = __float2bfloat16(v.z - __bfloat162float(h2));
    __nv_bfloat16 l3 = __float2bfloat16(v.w - __bfloat162float(h3));
    __nv_bfloat162 hp0; hp0.x = h0; hp0.y = h1;
    __nv_bfloat162 hp1; hp1.x = h2; hp1.y = h3;
    __nv_bfloat162 lp0; lp0.x = l0; lp0.y = l1;
    __nv_bfloat162 lp1; lp1.x = l2; lp1.y = l3;
    ((uint2*)hi)[i4] = make_uint2(*(uint32_t*)&hp0, *(uint32_t*)&hp1);
    ((uint2*)lo)[i4] = make_uint2(*(uint32_t*)&lp0, *(uint32_t*)&lp1);
}

// ===================== tensor-core GEMM (pre-split bf16, cp.async pipe) ======
#define KCH      32
#define W_STRIDE 40
#define X_STRIDE 136
#define ST_WHI   0
#define ST_WLO   10240
#define ST_XHI   20480
#define ST_XLO   29184
#define ST_SIZE  37888
#define SM_GEMM  (2 * ST_SIZE)

__global__ void __launch_bounds__(256, 2) gemm_bf3(
    const __nv_bfloat16* __restrict__ Whi, const __nv_bfloat16* __restrict__ Wlo,
    const __nv_bfloat16* __restrict__ Xhi_g, const __nv_bfloat16* __restrict__ Xlo_g,
    float* __restrict__ Cg, int Mw)
{
    extern __shared__ char sm[];
    const uint32_t smb = smem_u32(sm);

    const int tid  = threadIdx.x;
    const int lane = tid & 31;
    const int wid  = tid >> 5;
    const int wm   = wid >> 2;
    const int wn   = wid & 3;

    const int n0 = blockIdx.x * 128;
    const int m0 = blockIdx.y * 128;
    const __nv_bfloat16* Xhi = Xhi_g + (long)blockIdx.z * C_CH * HW;
    const __nv_bfloat16* Xlo = Xlo_g + (long)blockIdx.z * C_CH * HW;
    float* C = Cg + (long)blockIdx.z * (long)Mw * HW;

    float acc[4][4][4];
    #pragma unroll
    for (int i = 0; i < 4; i++)
        #pragma unroll
        for (int j = 0; j < 4; j++)
            #pragma unroll
            for (int r = 0; r < 4; r++) acc[i][j][r] = 0.f;

    const int a_row = (lane & 7) + ((lane >> 3) & 1) * 8;
    const int a_col = (lane >> 4) * 8;
    const int b_row = (lane & 7) + ((lane >> 3) & 1) * 8;
    const int b_col = (lane >> 4) * 8;

    auto load_chunk = [&](int kc, uint32_t stg) {
        const int k0 = kc * KCH;
        #pragma unroll
        for (int t = 0; t < 4; t++) {
            const int lin  = t * 256 + tid;
            const int row  = lin >> 3;
            const int spl  = (lin >> 2) & 1;
            const int seg  = lin & 3;
            const __nv_bfloat16* src =
                (spl ? Wlo : Whi) + (long)(m0 + row) * 128 + k0 + seg * 8;
            const uint32_t dst = smb + stg + (spl ? ST_WLO : ST_WHI)
                               + (row * W_STRIDE + seg * 8) * 2;
            cp_async16(dst, src);
        }
        #pragma unroll
        for (int t = 0; t < 4; t++) {
            const int lin  = t * 256 + tid;
            const int row  = lin >> 5;
            const int spl  = (lin >> 4) & 1;
            const int seg  = lin & 15;
            const __nv_bfloat16* src =
                (spl ? Xlo : Xhi) + (long)(k0 + row) * HW + n0 + seg * 8;
            const uint32_t dst = smb + stg + (spl ? ST_XLO : ST_XHI)
                               + (row * X_STRIDE + seg * 8) * 2;
            cp_async16(dst, src);
        }
    };

    load_chunk(0, 0);
    CP_COMMIT();

    #pragma unroll
    for (int kc = 0; kc < 4; kc++) {
        const uint32_t cur = (uint32_t)(kc & 1) * ST_SIZE;
        if (kc < 3) {
            load_chunk(kc + 1, (uint32_t)((kc + 1) & 1) * ST_SIZE);
            CP_COMMIT();
            CP_WAIT(1);
        } else {
            CP_WAIT(0);
        }
        __syncthreads();

        #pragma unroll
        for (int ks = 0; ks < 2; ks++) {
            const int kk = ks * 16;
            uint32_t a[4][4], bh[2][4], bl[2][4];

            #pragma unroll
            for (int u = 0; u < 2; u++) {
                const int r = kk + b_row;
                const int c = wn * 32 + u * 16 + b_col;
                ldsm_x4_t(bh[u], smb + cur + ST_XHI + (r * X_STRIDE + c) * 2);
                ldsm_x4_t(bl[u], smb + cur + ST_XLO + (r * X_STRIDE + c) * 2);
            }
            #pragma unroll
            for (int i = 0; i < 4; i++) {
                const int r = wm * 64 + i * 16 + a_row;
                ldsm_x4(a[i], smb + cur + ST_WHI + (r * W_STRIDE + kk + a_col) * 2);
            }
            // pass 1: hh — 16 independent MMAs (no acc reuse back-to-back)
            #pragma unroll
            for (int i = 0; i < 4; i++)
                #pragma unroll
                for (int j = 0; j < 4; j++)
                    mma_bf16(acc[i][j], a[i], &bh[j >> 1][(j & 1) * 2]);
            // pass 2: hl — acc reused only after 15 intervening MMAs
            #pragma unroll
            for (int i = 0; i < 4; i++)
                #pragma unroll
                for (int j = 0; j < 4; j++)
                    mma_bf16(acc[i][j], a[i], &bl[j >> 1][(j & 1) * 2]);
            #pragma unroll
            for (int i = 0; i < 4; i++) {
                const int r = wm * 64 + i * 16 + a_row;
                ldsm_x4(a[i], smb + cur + ST_WLO + (r * W_STRIDE + kk + a_col) * 2);
            }
            // pass 3: lh
            #pragma unroll
            for (int i = 0; i < 4; i++)
                #pragma unroll
                for (int j = 0; j < 4; j++)
                    mma_bf16(acc[i][j], a[i], &bh[j >> 1][(j & 1) * 2]);
        }
        __syncthreads();
    }

    const int mw = m0 + wm * 64;
    const int nw = n0 + wn * 32;
    #pragma unroll
    for (int i = 0; i < 4; i++) {
        #pragma unroll
        for (int j = 0; j < 4; j++) {
            const int row0 = mw + i * 16 + (lane >> 2);
            const int col  = nw + j * 8 + (lane & 3) * 2;
            *(float2*)&C[(long)row0 * HW + col]       = make_float2(acc[i][j][0], acc[i][j][1]);
            *(float2*)&C[(long)(row0 + 8) * HW + col] = make_float2(acc[i][j][2], acc[i][j][3]);
        }
    }
}

// ===================== depthwise 3x3 (SMEM-tiled, 16 rows/block) =============
__global__ void __launch_bounds__(256) dwconv3x3(
    const float* __restrict__ in,   // [B*384][128][128]
    const float* __restrict__ w,    // [384][1][3][3]
    float* __restrict__ out)
{
    __shared__ float s[18][128];

    const int bc = blockIdx.y;
    const int y0 = blockIdx.x * 16;
    const int ch = bc % QKV_CH;
    const int tid = threadIdx.x;

    const float* ip = in + (long)bc * HW;

    // stage rows y0-1 .. y0+16 (18 rows; zeros outside image)
    for (int t = tid; t < 576; t += 256) {
        const int r  = t >> 5;          // 0..17
        const int c4 = (t & 31) * 4;
        const int gy = y0 - 1 + r;
        float4 v = make_float4(0.f, 0.f, 0.f, 0.f);
        if (gy >= 0 && gy < 128) v = *(const float4*)&ip[gy * 128 + c4];
        *(float4*)&s[r][c4] = v;
    }

    const float* wp = w + ch * 9;
    const float w00 = wp[0], w01 = wp[1], w02 = wp[2];
    const float w10 = wp[3], w11 = wp[4], w12 = wp[5];
    const float w20 = wp[6], w21 = wp[7], w22 = wp[8];
    __syncthreads();

    const int x = (tid & 31) * 4;

    #pragma unroll
    for (int h = 0; h < 2; h++) {
        const int oy = (tid >> 5) + h * 8;  // 0..15
        float o0 = 0.f, o1 = 0.f, o2 = 0.f, o3 = 0.f;
        #pragma unroll
        for (int dy = 0; dy < 3; dy++) {
            const float* row = s[oy + dy];
            const float4 v = *(const float4*)&row[x];
            const float vl = (x > 0)   ? row[x - 1] : 0.f;
            const float vr = (x < 124) ? row[x + 4] : 0.f;
            const float wa = (dy == 0) ? w00 : (dy == 1) ? w10 : w20;
            const float wb = (dy == 0) ? w01 : (dy == 1) ? w11 : w21;
            const float wc = (dy == 0) ? w02 : (dy == 1) ? w12 : w22;
            o0 += vl  * wa + v.x * wb + v.y * wc;
            o1 += v.x * wa + v.y * wb + v.z * wc;
            o2 += v.y * wa + v.z * wb + v.w * wc;
            o3 += v.z * wa + v.w * wb + vr  * wc;
        }
        *(float4*)&out[(long)bc * HW + (y0 + oy) * 128 + x] = make_float4(o0, o1, o2, o3);
    }
}

// ===================== gram partials (register-tiled 4x4, float4) ============
// grid (NCHUNK, 64). Block: one (b,head), 1024-wide N chunk.
// Thread (ii,jj,tt): 4x4 (i,j) tile, tt = t-slice of 16.
__global__ void __launch_bounds__(256) gram16(
    const float* __restrict__ qkv2, float* __restrict__ partials)
{
    const int bh = blockIdx.y;
    const int b  = bh >> 3, hd = bh & 7;
    const int n0 = blockIdx.x * 1024;
    const float* qg = qkv2 + (long)b * QKV_CH * HW + (long)hd * DH * HW + n0;
    const float* kg = qg + (long)C_CH * HW;

    __shared__ float qs[16][132];
    __shared__ float ks[16][132];

    const int tid = threadIdx.x;
    const int tt = tid & 15;
    const int jj = (tid >> 4) & 3;
    const int ii = tid >> 6;

    float acc[4][4];
    #pragma unroll
    for (int a = 0; a < 4; a++)
        #pragma unroll
        for (int c = 0; c < 4; c++) acc[a][c] = 0.f;
    float nq[4] = {0.f, 0.f, 0.f, 0.f};
    float nk[4] = {0.f, 0.f, 0.f, 0.f};

    for (int t0 = 0; t0 < 1024; t0 += 128) {
        __syncthreads();
        #pragma unroll
        for (int st = 0; st < 2; st++) {
            const int idx = st * 256 + tid;        // 0..511
            const int r = idx >> 5, c4 = (idx & 31) * 4;
            *(float4*)&qs[r][c4] = *(const float4*)(qg + (long)r * HW + t0 + c4);
            *(float4*)&ks[r][c4] = *(const float4*)(kg + (long)r * HW + t0 + c4);
        }
        __syncthreads();
        #pragma unroll
        for (int u = 0; u < 2; u++) {
            const int c4 = (tt + u * 16) * 4;
            float4 q4[4], k4[4];
            #pragma unroll
            for (int r = 0; r < 4; r++) q4[r] = *(const float4*)&qs[ii * 4 + r][c4];
            #pragma unroll
            for (int r = 0; r < 4; r++) k4[r] = *(const float4*)&ks[jj * 4 + r][c4];
            #pragma unroll
            for (int a = 0; a < 4; a++)
                #pragma unroll
                for (int c = 0; c < 4; c++)
                    acc[a][c] += q4[a].x * k4[c].x + q4[a].y * k4[c].y
                               + q4[a].z * k4[c].z + q4[a].w * k4[c].w;
            if (jj == 0) {
                #pragma unroll
                for (int r = 0; r < 4; r++)
                    nq[r] += q4[r].x * q4[r].x + q4[r].y * q4[r].y
                           + q4[r].z * q4[r].z + q4[r].w * q4[r].w;
            }
            if (ii == 0) {
                #pragma unroll
                for (int r = 0; r < 4; r++)
                    nk[r] += k4[r].x * k4[r].x + k4[r].y * k4[r].y
                           + k4[r].z * k4[r].z + k4[r].w * k4[r].w;
            }
        }
    }

    // butterfly reduce over tt (16 lanes; masks stay within 16-lane halves)
    #pragma unroll
    for (int m = 1; m < 16; m <<= 1) {
        #pragma unroll
        for (int a = 0; a < 4; a++)
            #pragma unroll
            for (int c = 0; c < 4; c++)
                acc[a][c] += __shfl_xor_sync(0xFFFFFFFFu, acc[a][c], m);
        #pragma unroll
        for (int r = 0; r < 4; r++) {
            nq[r] += __shfl_xor_sync(0xFFFFFFFFu, nq[r], m);
            nk[r] += __shfl_xor_sync(0xFFFFFFFFu, nk[r], m);
        }
    }

    float* p = partials + ((long)bh * NCHUNK + blockIdx.x) * 288;
    if (tt == 0) {
        #pragma unroll
        for (int a = 0; a < 4; a++)
            #pragma unroll
            for (int c = 0; c < 4; c++)
                p[(ii * 4 + a) * 16 + jj * 4 + c] = acc[a][c];
        if (jj == 0) {
            #pragma unroll
            for (int r = 0; r < 4; r++) p[256 + ii * 4 + r] = nq[r];
        }
        if (ii == 0) {
            #pragma unroll
            for (int r = 0; r < 4; r++) p[256 + 16 + jj * 4 + r] = nk[r];
        }
    }
}

// ===================== softmax ==============================================
__global__ void __launch_bounds__(256) attn_softmax(
    const float* __restrict__ partials, const float* __restrict__ temperature,
    float* __restrict__ attn)
{
    const int bh = blockIdx.x;
    const int hd = bh & 7;
    __shared__ float S[256];
    __shared__ float qn[16], kn[16];
    const int tid = threadIdx.x;
    float s = 0.f;
    #pragma unroll
    for (int c = 0; c < NCHUNK; c++)
        s += partials[((long)bh * NCHUNK + c) * 288 + tid];
    S[tid] = s;
    if (tid < 32) {
        float ns = 0.f;
        #pragma unroll
        for (int c = 0; c < NCHUNK; c++)
            ns += partials[((long)bh * NCHUNK + c) * 288 + 256 + tid];
        const float nv = fmaxf(sqrtf(ns), 1e-12f);
        if (tid < 16) qn[tid] = nv; else kn[tid - 16] = nv;
    }
    __syncthreads();
    if (tid < 16) {
        const int   i  = tid;
        const float tp = temperature[hd];
        float lg[16];
        float mx = -1e30f;
        #pragma unroll
        for (int j = 0; j < 16; j++) {
            lg[j] = S[i * 16 + j] / (qn[i] * kn[j]) * tp;
            mx = fmaxf(mx, lg[j]);
        }
        float sum = 0.f;
        #pragma unroll
        for (int j = 0; j < 16; j++) { lg[j] = expf(lg[j] - mx); sum += lg[j]; }
        const float inv = 1.f / sum;
        #pragma unroll
        for (int j = 0; j < 16; j++)
            attn[(long)bh * 256 + i * 16 + j] = lg[j] * inv;
    }
}

// ===================== attn apply (writes bf16 hi/lo ctx) ====================
__global__ void __launch_bounds__(256) attn_apply_split(
    const float* __restrict__ qkv2, const float* __restrict__ illu,
    const float* __restrict__ attn,
    __nv_bfloat16* __restrict__ chi, __nv_bfloat16* __restrict__ clo)
{
    const int bh = blockIdx.y;
    const int b  = bh >> 3, hd = bh & 7;
    __shared__ float a[256];
    a[threadIdx.x] = attn[(long)bh * 256 + threadIdx.x];
    __syncthreads();
    const int n = blockIdx.x * 256 + threadIdx.x;
    const float* v  = qkv2 + (long)b * QKV_CH * HW + (long)(2 * C_CH + hd * DH) * HW + n;
    const float* il = illu + (long)b * C_CH   * HW + (long)(hd * DH) * HW + n;
    float vv[16];
    #pragma unroll
    for (int j = 0; j < 16; j++)
        vv[j] = v[(long)j * HW] * il[(long)j * HW];
    const long obase = (long)b * C_CH * HW + (long)(hd * DH) * HW + n;
    #pragma unroll
    for (int i = 0; i < 16; i++) {
        float s = 0.f;
        #pragma unroll
        for (int j = 0; j < 16; j++)
            s += a[i * 16 + j] * vv[j];
        const __nv_bfloat16 h = __float2bfloat16(s);
        const __nv_bfloat16 l = __float2bfloat16(s - __bfloat162float(h));
        chi[obase + (long)i * HW] = h;
        clo[obase + (long)i * HW] = l;
    }
}

// ===================== launch ===============================================
extern "C" void kernel_launch(void* const* d_in, const int* in_sizes, int n_in,
                              void* d_out, int out_size)
{
    const float* x_in   = (const float*)d_in[0];
    const float* illu   = (const float*)d_in[1];
    const float* w_qkv  = (const float*)d_in[2];
    const float* w_dw   = (const float*)d_in[3];
    const float* w_proj = (const float*)d_in[4];
    const float* temp   = (const float*)d_in[5];
    float* out = (float*)d_out;

    float *qkv, *qkv2, *part, *attn;
    __nv_bfloat16 *xhi, *xlo, *chi, *clo, *whi, *wlo;
    cudaGetSymbolAddress((void**)&qkv,  g_qkv);
    cudaGetSymbolAddress((void**)&qkv2, g_qkv2);
    cudaGetSymbolAddress((void**)&part, g_part);
    cudaGetSymbolAddress((void**)&attn, g_attn);
    cudaGetSymbolAddress((void**)&xhi,  g_xhi);
    cudaGetSymbolAddress((void**)&xlo,  g_xlo);
    cudaGetSymbolAddress((void**)&chi,  g_chi);
    cudaGetSymbolAddress((void**)&clo,  g_clo);
    cudaGetSymbolAddress((void**)&whi,  g_whi);
    cudaGetSymbolAddress((void**)&wlo,  g_wlo);

    cudaFuncSetAttribute(gemm_bf3, cudaFuncAttributeMaxDynamicSharedMemorySize, SM_GEMM);

    // 0) pre-split weights + input to bf16 hi/lo
    cvt_split<<<QKV_CH * C_CH / 1024, 256>>>(w_qkv, whi, wlo);
    cvt_split<<<C_CH * C_CH / 1024, 256>>>(w_proj, whi + QKV_CH * C_CH, wlo + QKV_CH * C_CH);
    cvt_split<<<BATCH * C_CH * HW / 1024, 256>>>(x_in, xhi, xlo);
    // 1) qkv = w_qkv @ x
    gemm_bf3<<<dim3(HW / 128, QKV_CH / 128, BATCH), 256, SM_GEMM>>>(whi, wlo, xhi, xlo, qkv, QKV_CH);
    // 2) depthwise 3x3 SAME (smem-tiled, 16 rows/block)
    dwconv3x3<<<dim3(8, BATCH * QKV_CH), 256>>>(qkv, w_dw, qkv2);
    // 3) gram partials + norms (register-tiled)
    gram16<<<dim3(NCHUNK, 64), 256>>>(qkv2, part);
    // 4) softmax
    attn_softmax<<<64, 256>>>(part, temp, attn);
    // 5) ctx = attn @ (v * illu), written as bf16 hi/lo
    attn_apply_split<<<dim3(HW / 256, 64), 256>>>(qkv2, illu, attn, chi, clo);
    // 6) out = w_proj @ ctx
    gemm_bf3<<<dim3(HW / 128, C_CH / 128, BATCH), 256, SM_GEMM>>>(
        whi + QKV_CH * C_CH, wlo + QKV_CH * C_CH, chi, clo, out, C_CH);
}

// round 8
// speedup vs baseline: 1.7688x; 1.1328x over previous
#include <cuda_runtime.h>
#include <cuda_bf16.h>
#include <cstdint>

#define C_CH   128
#define HW     16384
#define BATCH  8
#define QKV_CH 384
#define NHEAD  8
#define DH     16
#define NCHUNK 16

// ===================== scratch ==============================================
__device__ float g_qkv  [(long)BATCH * QKV_CH * HW];
__device__ float g_qkv2 [(long)BATCH * QKV_CH * HW];
__device__ float g_part [64 * NCHUNK * 288];
__device__ float g_attn [64 * 256];
__device__ __align__(16) __nv_bfloat16 g_whi   [QKV_CH * C_CH];
__device__ __align__(16) __nv_bfloat16 g_wlo   [QKV_CH * C_CH];
__device__ __align__(16) __nv_bfloat16 g_wehi  [BATCH * C_CH * C_CH];
__device__ __align__(16) __nv_bfloat16 g_welo  [BATCH * C_CH * C_CH];

// ===================== PTX helpers ==========================================
__device__ __forceinline__ uint32_t smem_u32(const void* p) {
    uint32_t a;
    asm("{ .reg .u64 t; cvta.to.shared.u64 t, %1; cvt.u32.u64 %0, t; }" : "=r"(a) : "l"(p));
    return a;
}
__device__ __forceinline__ void ldsm_x4(uint32_t* r, uint32_t addr) {
    asm volatile("ldmatrix.sync.aligned.m8n8.x4.shared.b16 {%0,%1,%2,%3}, [%4];"
                 : "=r"(r[0]), "=r"(r[1]), "=r"(r[2]), "=r"(r[3]) : "r"(addr));
}
__device__ __forceinline__ void ldsm_x4_t(uint32_t* r, uint32_t addr) {
    asm volatile("ldmatrix.sync.aligned.m8n8.x4.trans.shared.b16 {%0,%1,%2,%3}, [%4];"
                 : "=r"(r[0]), "=r"(r[1]), "=r"(r[2]), "=r"(r[3]) : "r"(addr));
}
__device__ __forceinline__ void mma_bf16(float* d, const uint32_t* a, const uint32_t* b) {
    asm volatile(
        "mma.sync.aligned.m16n8k16.row.col.f32.bf16.bf16.f32 "
        "{%0,%1,%2,%3}, {%4,%5,%6,%7}, {%8,%9}, {%0,%1,%2,%3};"
        : "+f"(d[0]), "+f"(d[1]), "+f"(d[2]), "+f"(d[3])
        : "r"(a[0]), "r"(a[1]), "r"(a[2]), "r"(a[3]), "r"(b[0]), "r"(b[1]));
}
__device__ __forceinline__ void cp_async16(uint32_t dst, const void* src) {
    asm volatile("cp.async.ca.shared.global [%0], [%1], 16;" :: "r"(dst), "l"(src));
}
#define CP_COMMIT() asm volatile("cp.async.commit_group;" ::: "memory")
#define CP_WAIT(n)  asm volatile("cp.async.wait_group %0;" :: "n"(n) : "memory")

__device__ __forceinline__ uint32_t split_hi2(float x, float y, float& rx, float& ry) {
    const __nv_bfloat16 hx = __float2bfloat16(x);
    const __nv_bfloat16 hy = __float2bfloat16(y);
    rx = x - __bfloat162float(hx);
    ry = y - __bfloat162float(hy);
    __nv_bfloat162 p; p.x = hx; p.y = hy;
    return *(uint32_t*)&p;
}
__device__ __forceinline__ uint32_t pack_bf2(float x, float y) {
    __nv_bfloat162 p; p.x = __float2bfloat16(x); p.y = __float2bfloat16(y);
    return *(uint32_t*)&p;
}

// ===================== split kernel: f32 -> bf16 hi + lo (weights) ==========
__global__ void __launch_bounds__(256) cvt_split(
    const float* __restrict__ in,
    __nv_bfloat16* __restrict__ hi, __nv_bfloat16* __restrict__ lo)
{
    const long i4 = (long)blockIdx.x * 256 + threadIdx.x;
    const float4 v = ((const float4*)in)[i4];
    float lx, ly, lz, lw;
    const uint32_t h0 = split_hi2(v.x, v.y, lx, ly);
    const uint32_t h1 = split_hi2(v.z, v.w, lz, lw);
    ((uint2*)hi)[i4] = make_uint2(h0, h1);
    ((uint2*)lo)[i4] = make_uint2(pack_bf2(lx, ly), pack_bf2(lz, lw));
}

// ===================== unified GEMM: C[z] = W[z] (MwxK128) @ X[z] (128xHW) ===
// W pre-split bf16 (full K resident in smem); X fp32, converted to hi/lo
// in-kernel during chunk staging (optionally gated by illu).
// 3-pass Ootomo: hh + hl + lh, fp32 acc. Block 128m x 128n, 8 warps 2m x 4n.
#define WS      136
#define XS      136
#define S_WHI   0
#define S_WLO   34816
#define S_XHI   69632
#define S_XLO   78336
#define SM_GEMM 87040

template<bool GATED>
__global__ void __launch_bounds__(256, 2) gemm_cvt(
    const __nv_bfloat16* __restrict__ Whi_g, const __nv_bfloat16* __restrict__ Wlo_g,
    long wz,
    const float* __restrict__ Xg, long xz,
    const float* __restrict__ Ig, long iz,
    float* __restrict__ Cg, int Mw)
{
    extern __shared__ char sm[];
    const uint32_t smb = smem_u32(sm);

    const int tid  = threadIdx.x;
    const int lane = tid & 31;
    const int wid  = tid >> 5;
    const int wm   = wid >> 2;
    const int wn   = wid & 3;
    const int n0   = blockIdx.x * 128;
    const int m0   = blockIdx.y * 128;
    const int z    = blockIdx.z;

    const __nv_bfloat16* Whi = Whi_g + (long)z * wz;
    const __nv_bfloat16* Wlo = Wlo_g + (long)z * wz;
    const float* X = Xg + (long)z * xz;
    const float* I = GATED ? (Ig + (long)z * iz) : nullptr;
    float* C = Cg + (long)z * (long)Mw * HW;

    // ---- W full-K tile (hi+lo) via cp.async, loaded once ----
    #pragma unroll
    for (int t = 0; t < 16; t++) {
        const int lin = t * 256 + tid;          // 0..4095
        const int spl = lin >> 11;
        const int row = (lin >> 4) & 127;
        const int seg = lin & 15;
        const __nv_bfloat16* src = (spl ? Wlo : Whi) + (long)(m0 + row) * 128 + seg * 8;
        const uint32_t dst = smb + (spl ? S_WLO : S_WHI) + (row * WS + seg * 8) * 2;
        cp_async16(dst, src);
    }
    CP_COMMIT();

    float acc[4][4][4];
    #pragma unroll
    for (int i = 0; i < 4; i++)
        #pragma unroll
        for (int j = 0; j < 4; j++)
            #pragma unroll
            for (int r = 0; r < 4; r++) acc[i][j][r] = 0.f;

    const int a_row = (lane & 7) + ((lane >> 3) & 1) * 8;
    const int a_col = (lane >> 4) * 8;
    const int b_row = (lane & 7) + ((lane >> 3) & 1) * 8;
    const int b_col = (lane >> 4) * 8;

    // X chunk staging mapping: 32 rows x 128 cols; thread does 4 rows x float4
    const int r0 = tid >> 5;            // 0..7
    const int c4 = (tid & 31) * 4;      // 0..124

    float4 xs[4], is_[4];
    #pragma unroll
    for (int rr = 0; rr < 4; rr++) {
        const int grow = r0 + rr * 8;
        xs[rr] = *(const float4*)(X + (long)grow * HW + n0 + c4);
        if (GATED) is_[rr] = *(const float4*)(I + (long)grow * HW + n0 + c4);
    }
    CP_WAIT(0);

    #pragma unroll
    for (int kc = 0; kc < 4; kc++) {
        // convert + STS current chunk
        #pragma unroll
        for (int rr = 0; rr < 4; rr++) {
            float4 v = xs[rr];
            if (GATED) { v.x *= is_[rr].x; v.y *= is_[rr].y; v.z *= is_[rr].z; v.w *= is_[rr].w; }
            float lx, ly, lz, lw;
            const uint32_t h0 = split_hi2(v.x, v.y, lx, ly);
            const uint32_t h1 = split_hi2(v.z, v.w, lz, lw);
            const int row = r0 + rr * 8;
            const uint32_t off = (uint32_t)(row * XS + c4) * 2;
            *(uint2*)(sm + S_XHI + off) = make_uint2(h0, h1);
            *(uint2*)(sm + S_XLO + off) = make_uint2(pack_bf2(lx, ly), pack_bf2(lz, lw));
        }
        __syncthreads();

        // prefetch next chunk (LDG latency hides behind MMA below)
        if (kc < 3) {
            #pragma unroll
            for (int rr = 0; rr < 4; rr++) {
                const int grow = (kc + 1) * 32 + r0 + rr * 8;
                xs[rr] = *(const float4*)(X + (long)grow * HW + n0 + c4);
                if (GATED) is_[rr] = *(const float4*)(I + (long)grow * HW + n0 + c4);
            }
        }

        #pragma unroll
        for (int ks = 0; ks < 2; ks++) {
            const int kk  = ks * 16;           // X tile row
            const int kkg = kc * 32 + kk;      // W smem col
            uint32_t a[4][4], bh[2][4], bl[2][4];

            #pragma unroll
            for (int u = 0; u < 2; u++) {
                const int r = kk + b_row;
                const int c = wn * 32 + u * 16 + b_col;
                ldsm_x4_t(bh[u], smb + S_XHI + (r * XS + c) * 2);
                ldsm_x4_t(bl[u], smb + S_XLO + (r * XS + c) * 2);
            }
            #pragma unroll
            for (int i = 0; i < 4; i++) {
                const int r = wm * 64 + i * 16 + a_row;
                ldsm_x4(a[i], smb + S_WHI + (r * WS + kkg + a_col) * 2);
            }
            #pragma unroll
            for (int i = 0; i < 4; i++)
                #pragma unroll
                for (int j = 0; j < 4; j++)
                    mma_bf16(acc[i][j], a[i], &bh[j >> 1][(j & 1) * 2]);
            #pragma unroll
            for (int i = 0; i < 4; i++)
                #pragma unroll
                for (int j = 0; j < 4; j++)
                    mma_bf16(acc[i][j], a[i], &bl[j >> 1][(j & 1) * 2]);
            #pragma unroll
            for (int i = 0; i < 4; i++) {
                const int r = wm * 64 + i * 16 + a_row;
                ldsm_x4(a[i], smb + S_WLO + (r * WS + kkg + a_col) * 2);
            }
            #pragma unroll
            for (int i = 0; i < 4; i++)
                #pragma unroll
                for (int j = 0; j < 4; j++)
                    mma_bf16(acc[i][j], a[i], &bh[j >> 1][(j & 1) * 2]);
        }
        __syncthreads();
    }

    const int mw = m0 + wm * 64;
    const int nw = n0 + wn * 32;
    #pragma unroll
    for (int i = 0; i < 4; i++) {
        #pragma unroll
        for (int j = 0; j < 4; j++) {
            const int row0 = mw + i * 16 + (lane >> 2);
            const int col  = nw + j * 8 + (lane & 3) * 2;
            *(float2*)&C[(long)row0 * HW + col]       = make_float2(acc[i][j][0], acc[i][j][1]);
            *(float2*)&C[(long)(row0 + 8) * HW + col] = make_float2(acc[i][j][2], acc[i][j][3]);
        }
    }
}

// ===================== depthwise 3x3 (SMEM-tiled, 16 rows/block) =============
__global__ void __launch_bounds__(256) dwconv3x3(
    const float* __restrict__ in, const float* __restrict__ w, float* __restrict__ out)
{
    __shared__ float s[18][128];

    const int bc = blockIdx.y;
    const int y0 = blockIdx.x * 16;
    const int ch = bc % QKV_CH;
    const int tid = threadIdx.x;
    const float* ip = in + (long)bc * HW;

    for (int t = tid; t < 576; t += 256) {
        const int r  = t >> 5;
        const int c4 = (t & 31) * 4;
        const int gy = y0 - 1 + r;
        float4 v = make_float4(0.f, 0.f, 0.f, 0.f);
        if (gy >= 0 && gy < 128) v = *(const float4*)&ip[gy * 128 + c4];
        *(float4*)&s[r][c4] = v;
    }

    const float* wp = w + ch * 9;
    const float w00 = wp[0], w01 = wp[1], w02 = wp[2];
    const float w10 = wp[3], w11 = wp[4], w12 = wp[5];
    const float w20 = wp[6], w21 = wp[7], w22 = wp[8];
    __syncthreads();

    const int x = (tid & 31) * 4;
    #pragma unroll
    for (int h = 0; h < 2; h++) {
        const int oy = (tid >> 5) + h * 8;
        float o0 = 0.f, o1 = 0.f, o2 = 0.f, o3 = 0.f;
        #pragma unroll
        for (int dy = 0; dy < 3; dy++) {
            const float* row = s[oy + dy];
            const float4 v = *(const float4*)&row[x];
            const float vl = (x > 0)   ? row[x - 1] : 0.f;
            const float vr = (x < 124) ? row[x + 4] : 0.f;
            const float wa = (dy == 0) ? w00 : (dy == 1) ? w10 : w20;
            const float wb = (dy == 0) ? w01 : (dy == 1) ? w11 : w21;
            const float wc = (dy == 0) ? w02 : (dy == 1) ? w12 : w22;
            o0 += vl  * wa + v.x * wb + v.y * wc;
            o1 += v.x * wa + v.y * wb + v.z * wc;
            o2 += v.y * wa + v.z * wb + v.w * wc;
            o3 += v.z * wa + v.w * wb + vr  * wc;
        }
        *(float4*)&out[(long)bc * HW + (y0 + oy) * 128 + x] = make_float4(o0, o1, o2, o3);
    }
}

// ===================== gram partials (register-tiled 4x4, float4) ============
__global__ void __launch_bounds__(256) gram16(
    const float* __restrict__ qkv2, float* __restrict__ partials)
{
    const int bh = blockIdx.y;
    const int b  = bh >> 3, hd = bh & 7;
    const int n0 = blockIdx.x * 1024;
    const float* qg = qkv2 + (long)b * QKV_CH * HW + (long)hd * DH * HW + n0;
    const float* kg = qg + (long)C_CH * HW;

    __shared__ float qs[16][132];
    __shared__ float ks[16][132];

    const int tid = threadIdx.x;
    const int tt = tid & 15;
    const int jj = (tid >> 4) & 3;
    const int ii = tid >> 6;

    float acc[4][4];
    #pragma unroll
    for (int a = 0; a < 4; a++)
        #pragma unroll
        for (int c = 0; c < 4; c++) acc[a][c] = 0.f;
    float nq[4] = {0.f, 0.f, 0.f, 0.f};
    float nk[4] = {0.f, 0.f, 0.f, 0.f};

    for (int t0 = 0; t0 < 1024; t0 += 128) {
        __syncthreads();
        #pragma unroll
        for (int st = 0; st < 2; st++) {
            const int idx = st * 256 + tid;
            const int r = idx >> 5, c4 = (idx & 31) * 4;
            *(float4*)&qs[r][c4] = *(const float4*)(qg + (long)r * HW + t0 + c4);
            *(float4*)&ks[r][c4] = *(const float4*)(kg + (long)r * HW + t0 + c4);
        }
        __syncthreads();
        #pragma unroll
        for (int u = 0; u < 2; u++) {
            const int c4 = (tt + u * 16) * 4;
            float4 q4[4], k4[4];
            #pragma unroll
            for (int r = 0; r < 4; r++) q4[r] = *(const float4*)&qs[ii * 4 + r][c4];
            #pragma unroll
            for (int r = 0; r < 4; r++) k4[r] = *(const float4*)&ks[jj * 4 + r][c4];
            #pragma unroll
            for (int a = 0; a < 4; a++)
                #pragma unroll
                for (int c = 0; c < 4; c++)
                    acc[a][c] += q4[a].x * k4[c].x + q4[a].y * k4[c].y
                               + q4[a].z * k4[c].z + q4[a].w * k4[c].w;
            if (jj == 0) {
                #pragma unroll
                for (int r = 0; r < 4; r++)
                    nq[r] += q4[r].x * q4[r].x + q4[r].y * q4[r].y
                           + q4[r].z * q4[r].z + q4[r].w * q4[r].w;
            }
            if (ii == 0) {
                #pragma unroll
                for (int r = 0; r < 4; r++)
                    nk[r] += k4[r].x * k4[r].x + k4[r].y * k4[r].y
                           + k4[r].z * k4[r].z + k4[r].w * k4[r].w;
            }
        }
    }

    #pragma unroll
    for (int m = 1; m < 16; m <<= 1) {
        #pragma unroll
        for (int a = 0; a < 4; a++)
            #pragma unroll
            for (int c = 0; c < 4; c++)
                acc[a][c] += __shfl_xor_sync(0xFFFFFFFFu, acc[a][c], m);
        #pragma unroll
        for (int r = 0; r < 4; r++) {
            nq[r] += __shfl_xor_sync(0xFFFFFFFFu, nq[r], m);
            nk[r] += __shfl_xor_sync(0xFFFFFFFFu, nk[r], m);
        }
    }

    float* p = partials + ((long)bh * NCHUNK + blockIdx.x) * 288;
    if (tt == 0) {
        #pragma unroll
        for (int a = 0; a < 4; a++)
            #pragma unroll
            for (int c = 0; c < 4; c++)
                p[(ii * 4 + a) * 16 + jj * 4 + c] = acc[a][c];
        if (jj == 0) {
            #pragma unroll
            for (int r = 0; r < 4; r++) p[256 + ii * 4 + r] = nq[r];
        }
        if (ii == 0) {
            #pragma unroll
            for (int r = 0; r < 4; r++) p[256 + 16 + jj * 4 + r] = nk[r];
        }
    }
}

// ===================== softmax ==============================================
__global__ void __launch_bounds__(256) attn_softmax(
    const float* __restrict__ partials, const float* __restrict__ temperature,
    float* __restrict__ attn)
{
    const int bh = blockIdx.x;
    const int hd = bh & 7;
    __shared__ float S[256];
    __shared__ float qn[16], kn[16];
    const int tid = threadIdx.x;
    float s = 0.f;
    #pragma unroll
    for (int c = 0; c < NCHUNK; c++)
        s += partials[((long)bh * NCHUNK + c) * 288 + tid];
    S[tid] = s;
    if (tid < 32) {
        float ns = 0.f;
        #pragma unroll
        for (int c = 0; c < NCHUNK; c++)
            ns += partials[((long)bh * NCHUNK + c) * 288 + 256 + tid];
        const float nv = fmaxf(sqrtf(ns), 1e-12f);
        if (tid < 16) qn[tid] = nv; else kn[tid - 16] = nv;
    }
    __syncthreads();
    if (tid < 16) {
        const int   i  = tid;
        const float tp = temperature[hd];
        float lg[16];
        float mx = -1e30f;
        #pragma unroll
        for (int j = 0; j < 16; j++) {
            lg[j] = S[i * 16 + j] / (qn[i] * kn[j]) * tp;
            mx = fmaxf(mx, lg[j]);
        }
        float sum = 0.f;
        #pragma unroll
        for (int j = 0; j < 16; j++) { lg[j] = expf(lg[j] - mx); sum += lg[j]; }
        const float inv = 1.f / sum;
        #pragma unroll
        for (int j = 0; j < 16; j++)
            attn[(long)bh * 256 + i * 16 + j] = lg[j] * inv;
    }
}

// ===================== Weff = W_proj @ blockdiag(attn)  =====================
// Weff[z][o][h*16+j] = sum_i W_proj[o][h*16+i] * attn[z*8+h][i][j]
__global__ void __launch_bounds__(256) weff_build(
    const float* __restrict__ wproj, const float* __restrict__ attn,
    __nv_bfloat16* __restrict__ whi, __nv_bfloat16* __restrict__ wlo)
{
    const int bh = blockIdx.x;      // z*8 + h
    const int h  = bh & 7, z = bh >> 3;
    __shared__ float at[16][16];
    __shared__ float wp[128][17];
    const int tid = threadIdx.x;

    at[tid >> 4][tid & 15] = attn[(long)bh * 256 + tid];
    #pragma unroll
    for (int t = 0; t < 8; t++) {
        const int idx = t * 256 + tid;
        const int o = idx >> 4, i = idx & 15;
        wp[o][i] = wproj[o * 128 + h * 16 + i];
    }
    __syncthreads();

    const int o  = tid >> 1;
    const int jb = (tid & 1) * 8;
    #pragma unroll
    for (int jj = 0; jj < 8; jj++) {
        const int j = jb + jj;
        float acc = 0.f;
        #pragma unroll
        for (int i = 0; i < 16; i++) acc += wp[o][i] * at[i][j];
        const __nv_bfloat16 hh = __float2bfloat16(acc);
        const __nv_bfloat16 ll = __float2bfloat16(acc - __bfloat162float(hh));
        const long oidx = ((long)z * 128 + o) * 128 + h * 16 + j;
        whi[oidx] = hh;
        wlo[oidx] = ll;
    }
}

// ===================== launch ===============================================
extern "C" void kernel_launch(void* const* d_in, const int* in_sizes, int n_in,
                              void* d_out, int out_size)
{
    const float* x_in   = (const float*)d_in[0];
    const float* illu   = (const float*)d_in[1];
    const float* w_qkv  = (const float*)d_in[2];
    const float* w_dw   = (const float*)d_in[3];
    const float* w_proj = (const float*)d_in[4];
    const float* temp   = (const float*)d_in[5];
    float* out = (float*)d_out;

    float *qkv, *qkv2, *part, *attn;
    __nv_bfloat16 *whi, *wlo, *wehi, *welo;
    cudaGetSymbolAddress((void**)&qkv,  g_qkv);
    cudaGetSymbolAddress((void**)&qkv2, g_qkv2);
    cudaGetSymbolAddress((void**)&part, g_part);
    cudaGetSymbolAddress((void**)&attn, g_attn);
    cudaGetSymbolAddress((void**)&whi,  g_whi);
    cudaGetSymbolAddress((void**)&wlo,  g_wlo);
    cudaGetSymbolAddress((void**)&wehi, g_wehi);
    cudaGetSymbolAddress((void**)&welo, g_welo);

    cudaFuncSetAttribute(gemm_cvt<false>, cudaFuncAttributeMaxDynamicSharedMemorySize, SM_GEMM);
    cudaFuncSetAttribute(gemm_cvt<true>,  cudaFuncAttributeMaxDynamicSharedMemorySize, SM_GEMM);

    // 0) pre-split qkv weights
    cvt_split<<<QKV_CH * C_CH / 1024, 256>>>(w_qkv, whi, wlo);
    // 1) qkv = w_qkv @ x (in-kernel fp32->hi/lo conversion of X)
    gemm_cvt<false><<<dim3(HW / 128, QKV_CH / 128, BATCH), 256, SM_GEMM>>>(
        whi, wlo, 0L, x_in, (long)C_CH * HW, nullptr, 0L, qkv, QKV_CH);
    // 2) depthwise 3x3 SAME
    dwconv3x3<<<dim3(8, BATCH * QKV_CH), 256>>>(qkv, w_dw, qkv2);
    // 3) gram partials + norms
    gram16<<<dim3(NCHUNK, 64), 256>>>(qkv2, part);
    // 4) softmax(16x16) with l2-norm + temperature
    attn_softmax<<<64, 256>>>(part, temp, attn);
    // 5) Weff[z] = W_proj @ blockdiag(attn[z])
    weff_build<<<64, 256>>>(w_proj, attn, wehi, welo);
    // 6) out = Weff[z] @ (v .* illu)   — gating fused into X staging
    gemm_cvt<true><<<dim3(HW / 128, 1, BATCH), 256, SM_GEMM>>>(
        wehi, welo, (long)C_CH * C_CH,
        qkv2 + 2L * C_CH * HW, (long)QKV_CH * HW,
        illu, (long)C_CH * HW, out, C_CH);
}